// round 11
// baseline (speedup 1.0000x reference)
#include <cuda_runtime.h>
#include <cuda_bf16.h>

// RoIPooling: crop_and_resize bilinear, POOL 7x7.
// feature_map: [B=8, H=64, W=64, C=256] fp32
// roi_bboxes:  [B=8, N=1000, 4] fp32 (y1,x1,y2,x2) normalized
// out:         [B, N, 7, 7, C] fp32
//
// R11: PERSISTENT single-wave kernel. 1184 CTAs x 8 warps = 9472 resident
// warps (8 CTAs/SM x 148 SMs); each warp grid-strides over the 112000
// (box, py, channel-half) row-tasks (~11.8 tasks/warp). Removes the ~5 CTA
// wave transitions (~2360 cyc each) and per-wave tail imbalance that the
// multi-wave launches paid. Inner body identical to R7 (proven fixed point:
// weight-form bilinear, 4-corner LDG.128 batch, 32 regs).

namespace {

constexpr int Hc = 64;
constexpr int Wc = 64;
constexpr int Cc = 256;          // channels
constexpr int CQ = Cc / 4;       // 64 float4 per pixel
constexpr int PH = 7;
constexpr int PW = 7;
constexpr int Bc = 8;
constexpr int Nc = 1000;
constexpr int NUM_TASKS = Bc * Nc * PH * 2;     // 112000 (2 channel-halves)
constexpr int WARPS_PER_BLOCK = 8;
constexpr int THREADS = WARPS_PER_BLOCK * 32;
constexpr int GRID = 1184;                      // 148 SMs x 8 CTAs: one wave
constexpr int TOTAL_WARPS = GRID * WARPS_PER_BLOCK;  // 9472

__global__ __launch_bounds__(THREADS, 8) void roi_pool_kernel(
    const float* __restrict__ fm,
    const float* __restrict__ boxes,
    float* __restrict__ out)
{
    const int warp0 = (blockIdx.x * WARPS_PER_BLOCK) + (threadIdx.x >> 5);
    const int lane = threadIdx.x & 31;

    const float hm1 = (float)(Hc - 1);
    const float wm1 = (float)(Wc - 1);
    const float4* fm4 = reinterpret_cast<const float4*>(fm);
    float4* o4 = reinterpret_cast<float4*>(out);

    for (int task = warp0; task < NUM_TASKS; task += TOTAL_WARPS) {
        // task = (box * PH + py) * 2 + half
        const int half = task & 1;
        const int row  = task >> 1;       // box * PH + py
        const int py   = row % PH;
        const int box  = row / PH;        // 0 .. B*N-1 (batch-major = output order)
        const int b    = box / Nc;

        // Box coords (16B aligned)
        const float4 bc = __ldg(reinterpret_cast<const float4*>(boxes) + box);
        const float by1 = bc.x, bx1 = bc.y, by2 = bc.z, bx2 = bc.w;

        // ---- y math: once per task (matches reference op order) ----
        const float y = by1 * hm1 + (float)py * ((by2 - by1) * hm1 / (float)(PH - 1));
        const float y0f = floorf(y);
        const float wy  = y - y0f;
        int y0 = (int)y0f;  y0 = min(max(y0, 0), Hc - 1);
        const int y1i = min(y0 + 1, Hc - 1);
        const bool valid_y = (y >= 0.0f) & (y <= hm1);
        const float omwy = 1.0f - wy;

        // quad index within the pixel handled by this lane
        const int q = half * 32 + lane;

        // 32-bit float4 offsets (fm = 8.4M float4, out = 100.4M float4 < 2^31)
        const int bbase = b * (Hc * Wc * CQ);
        const int rowT  = bbase + y0  * (Wc * CQ) + q;   // top row
        const int rowB  = bbase + y1i * (Wc * CQ) + q;   // bottom row

        // ---- x constants: once per task ----
        const float xbase = bx1 * wm1;
        const float dx    = (bx2 - bx1) * wm1 / (float)(PW - 1);

        unsigned int oofs = (unsigned int)row * (PW * CQ) + q;

        #pragma unroll 1
        for (int px = 0; px < PW; ++px) {
            const float x   = xbase + (float)px * dx;   // reference op order
            const float x0f = floorf(x);
            const float wx  = x - x0f;
            int x0 = (int)x0f;  x0 = min(max(x0, 0), Wc - 1);
            const int x1i = min(x0 + 1, Wc - 1);
            const float m = (valid_y & (x >= 0.0f) & (x <= wm1)) ? 1.0f : 0.0f;

            // Corner weights (warp-uniform per px), mask folded in.
            // m==0 -> all weights 0 -> r == 0 exactly.
            const float omwx = 1.0f - wx;
            const float w00 = omwx * omwy * m;
            const float w01 = wx   * omwy * m;
            const float w10 = omwx * wy   * m;
            const float w11 = wx   * wy   * m;

            const int x0q = x0  * CQ;
            const int x1q = x1i * CQ;

            // Front-batch the 4 corner loads (MLP = 4)
            const float4 a = __ldg(fm4 + rowT + x0q);
            const float4 bq= __ldg(fm4 + rowT + x1q);
            const float4 c = __ldg(fm4 + rowB + x0q);
            const float4 d = __ldg(fm4 + rowB + x1q);

            float4 r;
            r.x = fmaf(a.x, w00, fmaf(bq.x, w01, fmaf(c.x, w10, d.x * w11)));
            r.y = fmaf(a.y, w00, fmaf(bq.y, w01, fmaf(c.y, w10, d.y * w11)));
            r.z = fmaf(a.z, w00, fmaf(bq.z, w01, fmaf(c.z, w10, d.z * w11)));
            r.w = fmaf(a.w, w00, fmaf(bq.w, w01, fmaf(c.w, w10, d.w * w11)));

            // Streaming store: keep the 401MB output stream from evicting the
            // 33.5MB feature map out of L2 (gathers depend on L2 hits).
            __stcs(o4 + oofs, r);
            oofs += CQ;
        }
    }
}

} // namespace

extern "C" void kernel_launch(void* const* d_in, const int* in_sizes, int n_in,
                              void* d_out, int out_size) {
    const float* fm    = (const float*)d_in[0];
    const float* boxes = (const float*)d_in[1];
    float* out         = (float*)d_out;

    roi_pool_kernel<<<GRID, THREADS>>>(fm, boxes, out);
}

// round 12
// speedup vs baseline: 1.0714x; 1.0714x over previous
#include <cuda_runtime.h>
#include <cuda_bf16.h>

// RoIPooling: crop_and_resize bilinear, POOL 7x7.
// feature_map: [B=8, H=64, W=64, C=256] fp32
// roi_bboxes:  [B=8, N=1000, 4] fp32 (y1,x1,y2,x2) normalized
// out:         [B, N, 7, 7, C] fp32
//
// R12: R7 weight-form body + Blackwell packed f32x2 FMA (PTX-only; ptxas
// never auto-fuses). Corners loaded as ulonglong2 (same LDG.128), 4
// warp-uniform weights pre-packed as (w,w) u64 pairs, 16 scalar FFMA ->
// 8 FFMA2 per iteration. Cuts issued instructions ~17% without changing
// the proven memory structure (one warp per (box,py,channel-half),
// 4-corner batch). launch_bounds(256,7): 36-reg cap, 56 warps/SM.

namespace {

constexpr int Hc = 64;
constexpr int Wc = 64;
constexpr int Cc = 256;          // channels
constexpr int CQ = Cc / 4;       // 64 16B-quads per pixel
constexpr int PH = 7;
constexpr int PW = 7;
constexpr int Bc = 8;
constexpr int Nc = 1000;
constexpr int NUM_WARPS = Bc * Nc * PH * 2;     // 112000 (2 channel-halves)
constexpr int WARPS_PER_BLOCK = 8;
constexpr int THREADS = WARPS_PER_BLOCK * 32;

__device__ __forceinline__ unsigned long long ffma2(
    unsigned long long a, unsigned long long b, unsigned long long c)
{
    unsigned long long d;
    asm("fma.rn.f32x2 %0, %1, %2, %3;" : "=l"(d) : "l"(a), "l"(b), "l"(c));
    return d;
}

__device__ __forceinline__ unsigned long long fmul2(
    unsigned long long a, unsigned long long b)
{
    unsigned long long d;
    asm("mul.rn.f32x2 %0, %1, %2;" : "=l"(d) : "l"(a), "l"(b));
    return d;
}

__device__ __forceinline__ unsigned long long pack2(float w)
{
    unsigned long long r;
    asm("mov.b64 %0, {%1, %1};" : "=l"(r) : "f"(w));
    return r;
}

__global__ __launch_bounds__(THREADS, 7) void roi_pool_kernel(
    const float* __restrict__ fm,
    const float* __restrict__ boxes,
    float* __restrict__ out)
{
    const int gwarp = (blockIdx.x * WARPS_PER_BLOCK) + (threadIdx.x >> 5);
    const int lane = threadIdx.x & 31;

    // gwarp = (box * PH + py) * 2 + half   (grid is exact: no bounds guard)
    const int half = gwarp & 1;
    const int row  = gwarp >> 1;       // box * PH + py
    const int py   = row % PH;
    const int box  = row / PH;         // 0 .. B*N-1 (batch-major, matches output)
    const int b    = box / Nc;

    // Box coords (16B aligned)
    const float4 bc = __ldg(reinterpret_cast<const float4*>(boxes) + box);
    const float by1 = bc.x, bx1 = bc.y, by2 = bc.z, bx2 = bc.w;

    const float hm1 = (float)(Hc - 1);
    const float wm1 = (float)(Wc - 1);

    // ---- y math: once per warp (matches reference op order) ----
    const float y = by1 * hm1 + (float)py * ((by2 - by1) * hm1 / (float)(PH - 1));
    const float y0f = floorf(y);
    const float wy  = y - y0f;
    int y0 = (int)y0f;  y0 = min(max(y0, 0), Hc - 1);
    const int y1i = min(y0 + 1, Hc - 1);
    const bool valid_y = (y >= 0.0f) & (y <= hm1);
    const float omwy = 1.0f - wy;

    // quad index within the pixel handled by this lane
    const int q = half * 32 + lane;

    // 32-bit 16B-quad offsets (fm = 8.4M quads, out = 100.4M quads < 2^31)
    const ulonglong2* fm2 = reinterpret_cast<const ulonglong2*>(fm);
    const int bbase   = b * (Hc * Wc * CQ);
    const int rowT    = bbase + y0  * (Wc * CQ) + q;   // top row, this lane's quad
    const int rowB    = bbase + y1i * (Wc * CQ) + q;   // bottom row

    // ---- x constants: once per warp ----
    const float xbase = bx1 * wm1;
    const float dx    = (bx2 - bx1) * wm1 / (float)(PW - 1);

    unsigned int oofs = (unsigned int)row * (PW * CQ) + q;
    ulonglong2* o2 = reinterpret_cast<ulonglong2*>(out);

    #pragma unroll 1
    for (int px = 0; px < PW; ++px) {
        const float x   = xbase + (float)px * dx;   // same op order as reference
        const float x0f = floorf(x);
        const float wx  = x - x0f;
        int x0 = (int)x0f;  x0 = min(max(x0, 0), Wc - 1);
        const int x1i = min(x0 + 1, Wc - 1);
        const float m = (valid_y & (x >= 0.0f) & (x <= wm1)) ? 1.0f : 0.0f;

        // Corner weights (warp-uniform per px), mask folded in; packed as
        // (w,w) f32x2 pairs. m==0 -> all weights 0 -> r == 0 exactly.
        const float omwx = 1.0f - wx;
        const unsigned long long W00 = pack2(omwx * omwy * m);  // (y0,x0)
        const unsigned long long W01 = pack2(wx   * omwy * m);  // (y0,x1)
        const unsigned long long W10 = pack2(omwx * wy   * m);  // (y1,x0)
        const unsigned long long W11 = pack2(wx   * wy   * m);  // (y1,x1)

        const int x0q = x0  * CQ;
        const int x1q = x1i * CQ;

        // Front-batch the 4 corner loads (LDG.128, MLP = 4)
        const ulonglong2 a = __ldg(fm2 + rowT + x0q);
        const ulonglong2 bq= __ldg(fm2 + rowT + x1q);
        const ulonglong2 c = __ldg(fm2 + rowB + x0q);
        const ulonglong2 d = __ldg(fm2 + rowB + x1q);

        // 8x fma.rn.f32x2 instead of 16x FFMA (IEEE fma per component:
        // numerically identical to the scalar fmaf chain).
        ulonglong2 r;
        r.x = ffma2(a.x, W00, ffma2(bq.x, W01, ffma2(c.x, W10, fmul2(d.x, W11))));
        r.y = ffma2(a.y, W00, ffma2(bq.y, W01, ffma2(c.y, W10, fmul2(d.y, W11))));

        // Streaming store: keep the 401MB output stream from evicting the
        // 33.5MB feature map out of L2 (gathers depend on L2 hits).
        __stcs(o2 + oofs, r);
        oofs += CQ;
    }
}

} // namespace

extern "C" void kernel_launch(void* const* d_in, const int* in_sizes, int n_in,
                              void* d_out, int out_size) {
    const float* fm    = (const float*)d_in[0];
    const float* boxes = (const float*)d_in[1];
    float* out         = (float*)d_out;

    const int blocks = NUM_WARPS / WARPS_PER_BLOCK;  // 14000, exact
    roi_pool_kernel<<<blocks, THREADS>>>(fm, boxes, out);
}